// round 10
// baseline (speedup 1.0000x reference)
#include <cuda_runtime.h>
#include <cuda_fp16.h>
#include <stdint.h>

#define D      1024
#define NROWS  65536
#define DD     (D * D)

// GEMM tile: 128x128, BK=64, 3-stage cp.async, ldmatrix + XOR swizzle
#define TBK     64
#define KT      (D / TBK)        // 16
#define STAGEB  32768            // (128 rows A + 128 rows B) * 64 halves * 2B
#define SMEMSZ  (3 * STAGEB + 1024)

#define NCVTB   1024             // convert blocks co-scheduled in chain1 launch

// ---------------- scratch (static device globals; ALL 256B-aligned -------------
// cp.async 16B requires 16B-aligned global src; enforce regardless of link order)
__device__ __align__(256) __half g_xh[(size_t)NROWS * D];
__device__ __align__(256) __half g_gh[(size_t)NROWS * D];
__device__ __align__(256) __half g_Ah  [2 * DD];   // a = 10A
__device__ __align__(256) __half g_Bneg[2 * DD];   // -a
__device__ __align__(256) __half g_P2[2 * DD];     // a^2
__device__ __align__(256) __half g_ET[2 * DD];     // E^T = 0.1 a^2 - a
__device__ __align__(256) __half g_T [2 * DD];     // a^3 + 0.1 a^4
__device__ __align__(256) __half g_M [2 * DD];
__device__ __align__(256) float  g_part[2 * D];
__device__ __align__(256) float  g_pass[1];

__device__ __forceinline__ uint32_t smem_u32(const void* p) {
    return (uint32_t)__cvta_generic_to_shared(p);
}
#define LDSM_X4(r0, r1, r2, r3, addr) \
    asm volatile("ldmatrix.sync.aligned.m8n8.x4.shared.b16 {%0,%1,%2,%3}, [%4];" \
                 : "=r"(r0), "=r"(r1), "=r"(r2), "=r"(r3) : "r"(addr))
#define MMA16816(c0,c1,c2,c3,a0,a1,a2,a3,b0,b1) \
    asm volatile("mma.sync.aligned.m16n8k16.row.col.f32.f16.f16.f32 " \
        "{%0,%1,%2,%3}, {%4,%5,%6,%7}, {%8,%9}, {%0,%1,%2,%3};\n" \
        : "+f"(c0), "+f"(c1), "+f"(c2), "+f"(c3) \
        : "r"(a0), "r"(a1), "r"(a2), "r"(a3), "r"(b0), "r"(b1))

// ================= GEMM mainloop (shared by all GEMM kernels) ===================
struct GemmCtx {
    uint32_t sbase;
    int tid, wr, wc, grp, q, lrow, lk;
};

__device__ __forceinline__ GemmCtx make_ctx(uint32_t sbase) {
    GemmCtx cx;
    cx.sbase = sbase;
    cx.tid = threadIdx.x;
    int w = cx.tid >> 5, lane = cx.tid & 31;
    cx.wr = w >> 2; cx.wc = w & 3;
    cx.grp = lane >> 2; cx.q = lane & 3;
    cx.lrow = lane & 15; cx.lk = lane >> 4;
    return cx;
}

__device__ __forceinline__ void gemm_main(const GemmCtx& cx,
                                          const __half* __restrict__ A,
                                          const __half* __restrict__ B,
                                          size_t rowBase, int colBase,
                                          float acc[4][4][4])
{
    #pragma unroll
    for (int a = 0; a < 4; a++)
        #pragma unroll
        for (int b = 0; b < 4; b++)
            #pragma unroll
            for (int c = 0; c < 4; c++) acc[a][b][c] = 0.f;

    auto load_tile = [&](int kt) {
        const int stage = kt % 3;
        const int k0 = kt * TBK;
        #pragma unroll
        for (int i = 0; i < 8; i++) {
            int id  = cx.tid + (i << 8);
            int isB = id >> 10;
            int rc  = id & 1023;
            int row = rc >> 3, c = rc & 7;
            uint32_t sw = ((uint32_t)row << 7) | (((uint32_t)(c ^ (row & 7))) << 4);
            const __half* g = (isB ? (B + (size_t)(colBase + row) * D)
                                   : (A + (rowBase + row) * (size_t)D)) + k0 + (c << 3);
            uint32_t s = cx.sbase + stage * STAGEB + (isB << 14) + sw;
            asm volatile("cp.async.cg.shared.global [%0], [%1], 16;\n" :: "r"(s), "l"(g));
        }
        asm volatile("cp.async.commit_group;\n");
    };

    load_tile(0);
    load_tile(1);

    for (int kt = 0; kt < KT; kt++) {
        if (kt == KT - 1) asm volatile("cp.async.wait_group 0;\n");
        else              asm volatile("cp.async.wait_group 1;\n");
        __syncthreads();
        if (kt + 2 < KT) load_tile(kt + 2);

        const uint32_t aS = cx.sbase + (kt % 3) * STAGEB;
        const uint32_t bS = aS + 16384;

        #pragma unroll
        for (int kp = 0; kp < 4; kp++) {
            const uint32_t ch = (uint32_t)(kp * 2 + cx.lk);
            uint32_t a[4][4];
            #pragma unroll
            for (int mi = 0; mi < 4; mi++) {
                int row = cx.wr * 64 + mi * 16 + cx.lrow;
                uint32_t ad = aS + ((uint32_t)row << 7) + ((ch ^ (uint32_t)(row & 7)) << 4);
                LDSM_X4(a[mi][0], a[mi][1], a[mi][2], a[mi][3], ad);
            }
            uint32_t b[4][2];
            #pragma unroll
            for (int np = 0; np < 2; np++) {
                int row = cx.wc * 32 + np * 16 + cx.lrow;
                uint32_t bd = bS + ((uint32_t)row << 7) + ((ch ^ (uint32_t)(row & 7)) << 4);
                uint32_t r0, r1, r2, r3;
                LDSM_X4(r0, r1, r2, r3, bd);
                b[np * 2 + 0][0] = r0; b[np * 2 + 1][0] = r1;
                b[np * 2 + 0][1] = r2; b[np * 2 + 1][1] = r3;
            }
            #pragma unroll
            for (int mi = 0; mi < 4; mi++)
                #pragma unroll
                for (int ni = 0; ni < 4; ni++)
                    MMA16816(acc[mi][ni][0], acc[mi][ni][1], acc[mi][ni][2], acc[mi][ni][3],
                             a[mi][0], a[mi][1], a[mi][2], a[mi][3], b[ni][0], b[ni][1]);
        }
    }
}

// ---------------- prep: skew (8192 blocks) + row_sum (2048 blocks) --------------
__global__ void prep_kernel(const float* __restrict__ W1, const float* __restrict__ W2,
                            __half* __restrict__ Ah, __half* __restrict__ Bneg,
                            float* __restrict__ part) {
    int bid = blockIdx.x;
    if (bid < 8192) {
        int gidx = bid * 256 + threadIdx.x;
        int z = gidx >> 20;
        int idx = gidx & (DD - 1);
        const float* W = z ? W2 : W1;
        int i = idx >> 10, j = idx & (D - 1);
        float a = 5.0f * (W[idx] - W[j * D + i]);   // 10 * 0.5 * (W - W^T)
        Ah[gidx]   = __float2half(a);
        Bneg[gidx] = __float2half(-a);
    } else {
        int b = bid - 8192;
        const float* src = (b < D) ? (W1 + (size_t)b * D) : (W2 + (size_t)(b - D) * D);
        __shared__ float sm[256];
        float s = 0.f;
        for (int j = threadIdx.x; j < D; j += 256) s += src[j];
        sm[threadIdx.x] = s;
        __syncthreads();
        for (int o = 128; o > 0; o >>= 1) {
            if (threadIdx.x < o) sm[threadIdx.x] += sm[threadIdx.x + o];
            __syncthreads();
        }
        if (threadIdx.x == 0) part[b] = sm[0];
    }
}

// ---------------- chain stage 1 + convert_x + pass (one launch) -----------------
// bid 0..127   : GEMM  C = a @ a; epilogue: P2 = half(C), ET = half(0.1C - a)
// bid 128      : pass scalar reduction
// bid 129..    : convert x -> fp16 (64 stride-S float4 chunks per thread)
__global__ void __launch_bounds__(256, 2)
chain1_kernel(const __half* __restrict__ Ah, const __half* __restrict__ Bneg,
              __half* __restrict__ P2, __half* __restrict__ ET,
              const float* __restrict__ x, __half* __restrict__ xh,
              const float* __restrict__ part, const float* __restrict__ theta,
              float* __restrict__ pass)
{
    extern __shared__ char dsm_raw[];
    const int bid = blockIdx.x;
    const int tid = threadIdx.x;

    if (bid >= 129) {
        // -------- convert_x: 1024 blocks x 256 threads x 64 chunks = 2^24 float4
        const size_t S = (size_t)NCVTB * 256;            // 262144 chunks per sweep
        size_t i0 = (size_t)(bid - 129) * 256 + tid;
        #pragma unroll 4
        for (int k = 0; k < 64; k++) {
            size_t i = i0 + (size_t)k * S;
            float4 v = *(const float4*)(x + i * 4);
            union { __half2 h[2]; uint2 u; } w;
            w.h[0] = __floats2half2_rn(v.x, v.y);
            w.h[1] = __floats2half2_rn(v.z, v.w);
            *(uint2*)(xh + i * 4) = w.u;
        }
        return;
    }
    if (bid == 128) {
        // -------- passthrough scalar --------
        float* red = (float*)dsm_raw;
        float s = 0.f;
        for (int j = tid; j < 2 * D; j += 256) s += part[j];
        red[tid] = s;
        __syncthreads();
        for (int o = 128; o > 0; o >>= 1) {
            if (tid < o) red[tid] += red[tid + o];
            __syncthreads();
        }
        if (tid == 0) pass[0] = (red[0] / 1048576.0f + theta[0]) * 1e-6f;
        return;
    }

    // -------- chain GEMM 1: C = a @ (-a)^T = a^2 --------
    char* dsm = (char*)(((uintptr_t)dsm_raw + 1023) & ~(uintptr_t)1023);
    GemmCtx cx = make_ctx(smem_u32(dsm));
    const size_t loff = (size_t)(bid >> 6) * DD;
    const size_t rowBase = (size_t)((bid >> 3) & 7) * 128;
    const int    colBase = (bid & 7) * 128;

    float acc[4][4][4];
    gemm_main(cx, Ah + loff, Bneg + loff, rowBase, colBase, acc);

    const __half* Aeo = Ah + loff;
    __half* P2o = P2 + loff;
    __half* ETo = ET + loff;
    #pragma unroll
    for (int mi = 0; mi < 4; mi++) {
        const int rloc = cx.wr * 64 + mi * 16 + cx.grp;
        #pragma unroll
        for (int rr = 0; rr < 2; rr++) {
            const size_t grow = rowBase + rloc + rr * 8;
            #pragma unroll
            for (int ni = 0; ni < 4; ni++) {
                const int gcol = colBase + cx.wc * 32 + ni * 8 + cx.q * 2;
                float v0 = acc[mi][ni][rr * 2 + 0];
                float v1 = acc[mi][ni][rr * 2 + 1];
                const size_t idx = grow * D + gcol;
                *(__half2*)&P2o[idx] = __floats2half2_rn(v0, v1);
                __half2 a2 = *(const __half2*)&Aeo[idx];
                *(__half2*)&ETo[idx] = __floats2half2_rn(0.1f * v0 - __low2float(a2),
                                                         0.1f * v1 - __high2float(a2));
            }
        }
    }
}

// ---------------- chain stage 2: T = P2 @ ET^T = a^3 + 0.1 a^4 ------------------
__global__ void __launch_bounds__(256, 2)
chain2_kernel(const __half* __restrict__ P2, const __half* __restrict__ ET,
              __half* __restrict__ T)
{
    extern __shared__ char dsm_raw[];
    char* dsm = (char*)(((uintptr_t)dsm_raw + 1023) & ~(uintptr_t)1023);
    GemmCtx cx = make_ctx(smem_u32(dsm));
    const size_t loff = (size_t)blockIdx.z * DD;
    const size_t rowBase = (size_t)blockIdx.y * 128;
    const int    colBase = blockIdx.x * 128;

    float acc[4][4][4];
    gemm_main(cx, P2 + loff, ET + loff, rowBase, colBase, acc);

    __half* To = T + loff;
    #pragma unroll
    for (int mi = 0; mi < 4; mi++) {
        const int rloc = cx.wr * 64 + mi * 16 + cx.grp;
        #pragma unroll
        for (int rr = 0; rr < 2; rr++) {
            const size_t grow = rowBase + rloc + rr * 8;
            #pragma unroll
            for (int ni = 0; ni < 4; ni++) {
                const int gcol = colBase + cx.wc * 32 + ni * 8 + cx.q * 2;
                *(__half2*)&To[grow * D + gcol] =
                    __floats2half2_rn(acc[mi][ni][rr * 2], acc[mi][ni][rr * 2 + 1]);
            }
        }
    }
}

// M = 0.2*a + 0.02*P2 + 2e-3*T
__global__ void combine_kernel(const __half* __restrict__ Ah, const __half* __restrict__ P2,
                               const __half* __restrict__ T, __half* __restrict__ M) {
    size_t i = ((size_t)blockIdx.x * blockDim.x + threadIdx.x) * 2;
    float2 a  = __half22float2(*(const __half2*)&Ah[i]);
    float2 p2 = __half22float2(*(const __half2*)&P2[i]);
    float2 t  = __half22float2(*(const __half2*)&T[i]);
    *(__half2*)&M[i] = __floats2half2_rn(0.2f*a.x + 0.02f*p2.x + 2e-3f*t.x,
                                         0.2f*a.y + 0.02f*p2.y + 2e-3f*t.y);
}

// ---------------- big GEMMs ------------------------------------------------------
// EPI 1: h = C + ident; rotate by theta; OutH = half(h)
// EPI 2: OutF = C + ident + passv
template <int EPI>
__global__ void __launch_bounds__(256, 2)
big_gemm(const __half* __restrict__ Aop, const __half* __restrict__ Bop,
         const __half* __restrict__ ident, const float* __restrict__ theta,
         const float* __restrict__ passv,
         __half* __restrict__ OutH, float* __restrict__ OutF)
{
    extern __shared__ char dsm_raw[];
    char* dsm = (char*)(((uintptr_t)dsm_raw + 1023) & ~(uintptr_t)1023);
    GemmCtx cx = make_ctx(smem_u32(dsm));
    const size_t rowBase = (size_t)blockIdx.y * 128;
    const int    colBase = blockIdx.x * 128;

    float acc[4][4][4];
    gemm_main(cx, Aop, Bop, rowBase, colBase, acc);

    float cs = 0.f, sn = 0.f, pv = 0.f;
    if (EPI == 1) { float th = theta[0]; cs = cosf(th); sn = sinf(th); }
    if (EPI == 2) { pv = passv[0]; }

    #pragma unroll
    for (int mi = 0; mi < 4; mi++) {
        const int rloc = cx.wr * 64 + mi * 16 + cx.grp;
        #pragma unroll
        for (int rr = 0; rr < 2; rr++) {
            const size_t grow = rowBase + rloc + rr * 8;
            #pragma unroll
            for (int ni = 0; ni < 4; ni++) {
                const int gcol = colBase + cx.wc * 32 + ni * 8 + cx.q * 2;
                float v0 = acc[mi][ni][rr * 2 + 0];
                float v1 = acc[mi][ni][rr * 2 + 1];
                const size_t idx = grow * D + gcol;
                __half2 id = *(const __half2*)&ident[idx];
                if (EPI == 1) {
                    float h0 = v0 + __low2float(id);
                    float h1 = v1 + __high2float(id);
                    *(__half2*)&OutH[idx] = __floats2half2_rn(cs * h0 - sn * h1,
                                                              sn * h0 + cs * h1);
                } else {
                    float2 o;
                    o.x = v0 + __low2float(id) + pv;
                    o.y = v1 + __high2float(id) + pv;
                    *(float2*)&OutF[idx] = o;
                }
            }
        }
    }
}

// ---------------- host launcher ------------------------------------------------

extern "C" void kernel_launch(void* const* d_in, const int* in_sizes, int n_in,
                              void* d_out, int out_size) {
    const float* x     = (const float*)d_in[0];
    const float* u1    = (const float*)d_in[1];
    const float* u2    = (const float*)d_in[2];
    const float* theta = (const float*)d_in[3];
    float* out = (float*)d_out;

    __half *xh, *gh, *Ah, *Bneg, *P2, *ET, *T, *M;
    float *part, *pass;
    cudaGetSymbolAddress((void**)&xh,   g_xh);
    cudaGetSymbolAddress((void**)&gh,   g_gh);
    cudaGetSymbolAddress((void**)&Ah,   g_Ah);
    cudaGetSymbolAddress((void**)&Bneg, g_Bneg);
    cudaGetSymbolAddress((void**)&P2,   g_P2);
    cudaGetSymbolAddress((void**)&ET,   g_ET);
    cudaGetSymbolAddress((void**)&T,    g_T);
    cudaGetSymbolAddress((void**)&M,    g_M);
    cudaGetSymbolAddress((void**)&part, g_part);
    cudaGetSymbolAddress((void**)&pass, g_pass);

    cudaFuncSetAttribute(chain1_kernel, cudaFuncAttributeMaxDynamicSharedMemorySize, SMEMSZ);
    cudaFuncSetAttribute(chain2_kernel, cudaFuncAttributeMaxDynamicSharedMemorySize, SMEMSZ);
    cudaFuncSetAttribute(big_gemm<1>,   cudaFuncAttributeMaxDynamicSharedMemorySize, SMEMSZ);
    cudaFuncSetAttribute(big_gemm<2>,   cudaFuncAttributeMaxDynamicSharedMemorySize, SMEMSZ);

    // skew (a = 10A, -a) + row sums, one launch
    prep_kernel<<<8192 + 2048, 256>>>(u1, u2, Ah, Bneg, part);

    // chain GEMM1 (P2 = a^2, ET = 0.1 a^2 - a) + convert_x + pass scalar, one launch
    chain1_kernel<<<129 + NCVTB, 256, SMEMSZ>>>(Ah, Bneg, P2, ET, x, xh, part, theta, pass);

    // chain GEMM2: T = P2 @ ET^T = a^3 + 0.1 a^4
    chain2_kernel<<<dim3(8, 8, 2), 256, SMEMSZ>>>(P2, ET, T);

    // M = 0.2 a + 0.02 a^2 + 2e-3 T
    combine_kernel<<<2 * DD / 512, 256>>>(Ah, P2, T, M);

    // layer 1: g = rotate(x + x @ M1^T, theta)
    const dim3 gbig(D / 128, NROWS / 128);   // 8 x 512
    big_gemm<1><<<gbig, 256, SMEMSZ>>>(xh, M, xh, theta, nullptr, gh, nullptr);
    // layer 2: out = g + g @ M2^T + passthrough
    big_gemm<2><<<gbig, 256, SMEMSZ>>>(gh, M + DD, gh, nullptr, pass, nullptr, out);
}